// round 1
// baseline (speedup 1.0000x reference)
#include <cuda_runtime.h>
#include <cstdint>
#include <cstddef>

#define NA_N 100000
#define NB_N 100000
#define ND_N 50000
#define HDIM 128
#define ODIM 16
#define EMAX 600000

// ------------------------- scratch (static device globals; no allocation) ----
__device__ float g_aggd[(size_t)ND_N * 256];      // layer0 concat aggregates [50000,256]
__device__ float g_h1d[(size_t)ND_N * HDIM];      // h1['d']
__device__ float g_ha[(size_t)NA_N * HDIM];       // agg for 'a' then h2['a'] in-place
__device__ float g_hb[(size_t)NB_N * HDIM];
__device__ float g_ta[(size_t)NA_N * ODIM];       // h2_a @ W2[0]
__device__ float g_tb[(size_t)NB_N * ODIM];
__device__ float g_agg2[(size_t)ND_N * ODIM];
__device__ float g_agg3[(size_t)ND_N * ODIM];

__device__ int g_deg0[ND_N], g_deg1[ND_N], g_dega[NA_N], g_degb[NB_N];
__device__ int g_cnt0[ND_N], g_cnt1[ND_N], g_cnt2[NA_N], g_cnt3[NB_N];
__device__ int g_off0[ND_N + 1], g_off1[ND_N + 1], g_off2[NA_N + 1], g_off3[NB_N + 1];
__device__ int g_csr0[EMAX], g_csr1[EMAX], g_csr2[EMAX], g_csr3[EMAX];
__device__ int g_part[256];

__device__ float g_W0[256 * 128];    // [k=r*128+i][o]  (W0[0] rows then W0[1])
__device__ float g_W1a[128 * 128];   // W1[2]
__device__ float g_W1b[128 * 128];   // W1[3]
__device__ float g_W2a[128 * 16];    // W2[0]
__device__ float g_W2b[128 * 16];    // W2[1]

// ------------------------- small utility kernels -----------------------------
__global__ void zero_ints_kernel() {
    int i = blockIdx.x * blockDim.x + threadIdx.x;
    int st = gridDim.x * blockDim.x;
    for (int j = i; j < ND_N; j += st) { g_deg0[j] = 0; g_deg1[j] = 0; g_cnt0[j] = 0; g_cnt1[j] = 0; }
    for (int j = i; j < NA_N; j += st) { g_dega[j] = 0; g_degb[j] = 0; g_cnt2[j] = 0; g_cnt3[j] = 0; }
}

__global__ void hist_kernel(const int* __restrict__ dst, int n, int* __restrict__ deg) {
    int e = blockIdx.x * blockDim.x + threadIdx.x;
    if (e < n) atomicAdd(&deg[dst[e]], 1);
}

// exclusive scan of deg[0..n) into off[0..n]; 3 phases
__global__ __launch_bounds__(1024) void scan_phase1(const int* __restrict__ deg, int n, int* __restrict__ part) {
    __shared__ int s[1024];
    int i = blockIdx.x * 1024 + threadIdx.x;
    s[threadIdx.x] = (i < n) ? deg[i] : 0;
    __syncthreads();
    for (int o = 512; o > 0; o >>= 1) {
        if (threadIdx.x < o) s[threadIdx.x] += s[threadIdx.x + o];
        __syncthreads();
    }
    if (threadIdx.x == 0) part[blockIdx.x] = s[0];
}

__global__ void scan_phase2(int* part, int nb, int* off, int n) {
    if (threadIdx.x == 0 && blockIdx.x == 0) {
        int run = 0;
        for (int b = 0; b < nb; b++) { int t = part[b]; part[b] = run; run += t; }
        off[n] = run;
    }
}

__global__ __launch_bounds__(1024) void scan_phase3(const int* __restrict__ deg, int n,
                                                    const int* __restrict__ part, int* __restrict__ off) {
    __shared__ int s[1024];
    int tid = threadIdx.x;
    int i = blockIdx.x * 1024 + tid;
    int v = (i < n) ? deg[i] : 0;
    s[tid] = v;
    __syncthreads();
    for (int o = 1; o < 1024; o <<= 1) {
        int t = (tid >= o) ? s[tid - o] : 0;
        __syncthreads();
        s[tid] += t;
        __syncthreads();
    }
    if (i < n) off[i] = part[blockIdx.x] + s[tid] - v;   // exclusive
}

__global__ void scatter_kernel(const int* __restrict__ src, const int* __restrict__ dst, int n,
                               const int* __restrict__ off, int* __restrict__ cnt, int* __restrict__ csr) {
    int e = blockIdx.x * blockDim.x + threadIdx.x;
    if (e < n) {
        int d = dst[e];
        int slot = atomicAdd(&cnt[d], 1);
        csr[off[d] + slot] = src[e];
    }
}

// deterministic order within each dst row (fp-sum order fixed across launches)
__global__ void sortrows_kernel(const int* __restrict__ off, int* __restrict__ csr, int nd) {
    int d = blockIdx.x * blockDim.x + threadIdx.x;
    if (d >= nd) return;
    int b = off[d], e = off[d + 1];
    for (int i = b + 1; i < e; i++) {
        int v = csr[i];
        int j = i - 1;
        while (j >= b && csr[j] > v) { csr[j + 1] = csr[j]; j--; }
        csr[j + 1] = v;
    }
}

// W_r = coef[r,0]*basis[0] + coef[r,1]*basis[1]
__global__ void build_w_kernel(const float* __restrict__ basis, const float* __restrict__ coef,
                               int r, int tot, float* __restrict__ out, int outoff) {
    int idx = blockIdx.x * blockDim.x + threadIdx.x;
    if (idx < tot) {
        float c0 = coef[r * 2 + 0], c1 = coef[r * 2 + 1];
        out[outoff + idx] = c0 * basis[idx] + c1 * basis[tot + idx];
    }
}

// ------------------------- aggregation (gather-only, no atomics) -------------
__global__ void agg_csr128_kernel(const float* __restrict__ feat, const int* __restrict__ off,
                                  const int* __restrict__ csr, int nd,
                                  float* __restrict__ out, int ldo, int coloff) {
    int warp = (blockIdx.x * blockDim.x + threadIdx.x) >> 5;
    int lane = threadIdx.x & 31;
    if (warp >= nd) return;
    int b = off[warp], e = off[warp + 1];
    float4 acc = make_float4(0.f, 0.f, 0.f, 0.f);
    for (int j = b; j < e; j++) {
        int s = csr[j];
        float4 v = *(const float4*)(feat + (size_t)s * HDIM + lane * 4);
        acc.x += v.x; acc.y += v.y; acc.z += v.z; acc.w += v.w;
    }
    *(float4*)(out + (size_t)warp * ldo + coloff + lane * 4) = acc;
}

__global__ void agg_csr16_kernel(const float* __restrict__ feat, const int* __restrict__ off,
                                 const int* __restrict__ csr, int nd, float* __restrict__ out) {
    int g = (blockIdx.x * blockDim.x + threadIdx.x) >> 2;
    int sl = threadIdx.x & 3;
    if (g >= nd) return;
    int b = off[g], e = off[g + 1];
    float4 acc = make_float4(0.f, 0.f, 0.f, 0.f);
    for (int j = b; j < e; j++) {
        int s = csr[j];
        float4 v = *(const float4*)(feat + (size_t)s * ODIM + sl * 4);
        acc.x += v.x; acc.y += v.y; acc.z += v.z; acc.w += v.w;
    }
    *(float4*)(out + (size_t)g * ODIM + sl * 4) = acc;
}

// ------------------------- GEMM (fp32, smem-tiled) ---------------------------
// Out[M,128] = scale(A[M,K]) @ W[K,128] (+bias, relu). Per-row scale folded in:
// columns k < kHalf use 1/max(degA,1), k >= kHalf use 1/max(degB,1).
#define GTM 64
#define GKC 32
__global__ __launch_bounds__(256) void gemm128_kernel(
    const float* A, int M, int K,
    const int* degA, const int* degB, int kHalf,
    const float* __restrict__ W, const float* __restrict__ bias,
    int doRelu, float* Out)
{
    __shared__ float As[GTM][GKC + 4];
    __shared__ float Bs[GKC][128];
    __shared__ float s0s[GTM], s1s[GTM];

    int tid = threadIdx.x;
    int tx = tid & 15;     // col group: 8 cols
    int ty = tid >> 4;     // row group: 4 rows
    int row0 = blockIdx.x * GTM;

    if (tid < GTM) {
        int r = row0 + tid;
        float a = 1.f, b = 1.f;
        if (r < M) {
            if (degA) a = 1.f / fmaxf((float)degA[r], 1.f);
            if (degB) b = 1.f / fmaxf((float)degB[r], 1.f); else b = a;
        }
        s0s[tid] = a; s1s[tid] = b;
    }
    __syncthreads();

    float acc[4][8];
#pragma unroll
    for (int i = 0; i < 4; i++)
#pragma unroll
        for (int j = 0; j < 8; j++) acc[i][j] = 0.f;

    for (int k0 = 0; k0 < K; k0 += GKC) {
#pragma unroll
        for (int l = 0; l < 2; l++) {
            int idx = tid + l * 256;      // 0..511 -> (row, kvec)
            int r = idx >> 3;
            int kv = idx & 7;
            int gk = k0 + kv * 4;
            float4 v = make_float4(0.f, 0.f, 0.f, 0.f);
            int gr = row0 + r;
            if (gr < M) v = *(const float4*)(A + (size_t)gr * K + gk);
            float s = (gk < kHalf) ? s0s[r] : s1s[r];
            v.x *= s; v.y *= s; v.z *= s; v.w *= s;
            *(float4*)&As[r][kv * 4] = v;
        }
#pragma unroll
        for (int l = 0; l < 4; l++) {
            int idx = tid + l * 256;      // 0..1023 -> (kk, colvec)
            int kk = idx >> 5;
            int cv = idx & 31;
            *(float4*)&Bs[kk][cv * 4] = *(const float4*)(W + (size_t)(k0 + kk) * 128 + cv * 4);
        }
        __syncthreads();
#pragma unroll
        for (int kk = 0; kk < GKC; kk++) {
            float aa[4];
            aa[0] = As[ty * 4 + 0][kk];
            aa[1] = As[ty * 4 + 1][kk];
            aa[2] = As[ty * 4 + 2][kk];
            aa[3] = As[ty * 4 + 3][kk];
            float4 b0 = *(float4*)&Bs[kk][tx * 8];
            float4 b1 = *(float4*)&Bs[kk][tx * 8 + 4];
            float bb[8] = {b0.x, b0.y, b0.z, b0.w, b1.x, b1.y, b1.z, b1.w};
#pragma unroll
            for (int i = 0; i < 4; i++)
#pragma unroll
                for (int j = 0; j < 8; j++) acc[i][j] += aa[i] * bb[j];
        }
        __syncthreads();
    }

#pragma unroll
    for (int i = 0; i < 4; i++) {
        int r = row0 + ty * 4 + i;
        if (r < M) {
#pragma unroll
            for (int j = 0; j < 8; j++) {
                float v = acc[i][j] + bias[tx * 8 + j];
                if (doRelu) v = fmaxf(v, 0.f);
                Out[(size_t)r * 128 + tx * 8 + j] = v;
            }
        }
    }
}

// Out[M,16] = A[M,128] @ W[128,16]  (no bias/relu/scale)
__global__ __launch_bounds__(256) void gemm16_kernel(const float* __restrict__ A, int M,
                                                     const float* __restrict__ W, float* __restrict__ Out) {
    __shared__ float As[32][132];
    __shared__ float Wt[16][132];
    int tid = threadIdx.x;
    for (int idx = tid; idx < 2048; idx += 256) {
        int k = idx >> 4, c = idx & 15;
        Wt[c][k] = W[idx];
    }
    int row0 = blockIdx.x * 32;
#pragma unroll
    for (int l = 0; l < 4; l++) {
        int idx = tid + l * 256;
        int r = idx >> 5;
        int kv = idx & 31;
        float4 v = make_float4(0.f, 0.f, 0.f, 0.f);
        if (row0 + r < M) v = *(const float4*)(A + (size_t)(row0 + r) * 128 + kv * 4);
        *(float4*)&As[r][kv * 4] = v;
    }
    __syncthreads();
    int r = tid >> 4;   // 0..15 (rows r and r+16)
    int c = tid & 15;
    float acc0 = 0.f, acc1 = 0.f;
#pragma unroll
    for (int k = 0; k < 128; k += 4) {
        float4 w = *(float4*)&Wt[c][k];
        float4 a0 = *(float4*)&As[r][k];
        float4 a1 = *(float4*)&As[r + 16][k];
        acc0 += a0.x * w.x + a0.y * w.y + a0.z * w.z + a0.w * w.w;
        acc1 += a1.x * w.x + a1.y * w.y + a1.z * w.z + a1.w * w.w;
    }
    if (row0 + r < M)      Out[(size_t)(row0 + r) * 16 + c] = acc0;
    if (row0 + r + 16 < M) Out[(size_t)(row0 + r + 16) * 16 + c] = acc1;
}

// out[i,c] = agg2[i,c]/max(deg0,1) + agg3[i,c]/max(deg1,1) + bias2[c]
__global__ void combine_kernel(const float* __restrict__ agg2, const float* __restrict__ agg3,
                               const int* __restrict__ deg0, const int* __restrict__ deg1,
                               const float* __restrict__ bias2, float* __restrict__ out, int n) {
    int idx = blockIdx.x * blockDim.x + threadIdx.x;
    if (idx >= n) return;
    int i = idx >> 4;
    int c = idx & 15;
    float inv0 = 1.f / fmaxf((float)deg0[i], 1.f);
    float inv1 = 1.f / fmaxf((float)deg1[i], 1.f);
    out[idx] = agg2[idx] * inv0 + agg3[idx] * inv1 + bias2[c];
}

// ------------------------- host driver ---------------------------------------
static inline int cdiv(int a, int b) { return (a + b - 1) / b; }

extern "C" void kernel_launch(void* const* d_in, const int* in_sizes, int n_in,
                              void* d_out, int out_size) {
    (void)n_in; (void)out_size;
    const float* feat_a = (const float*)d_in[0];
    const float* feat_b = (const float*)d_in[1];
    const float* basis0 = (const float*)d_in[3];
    const float* coef0  = (const float*)d_in[4];
    const float* bias0  = (const float*)d_in[5];
    const float* basis1 = (const float*)d_in[6];
    const float* coef1  = (const float*)d_in[7];
    const float* bias1  = (const float*)d_in[8];
    const float* basis2 = (const float*)d_in[9];
    const float* coef2  = (const float*)d_in[10];
    const float* bias2  = (const float*)d_in[11];
    const int* e_src[4] = {(const int*)d_in[12], (const int*)d_in[14], (const int*)d_in[16], (const int*)d_in[18]};
    const int* e_dst[4] = {(const int*)d_in[13], (const int*)d_in[15], (const int*)d_in[17], (const int*)d_in[19]};
    int nE[4] = {in_sizes[12], in_sizes[14], in_sizes[16], in_sizes[18]};
    float* out = (float*)d_out;

    // resolve scratch addresses
    void* p;
    cudaGetSymbolAddress(&p, g_aggd);  float* aggd = (float*)p;
    cudaGetSymbolAddress(&p, g_h1d);   float* h1d  = (float*)p;
    cudaGetSymbolAddress(&p, g_ha);    float* ha   = (float*)p;
    cudaGetSymbolAddress(&p, g_hb);    float* hb   = (float*)p;
    cudaGetSymbolAddress(&p, g_ta);    float* ta   = (float*)p;
    cudaGetSymbolAddress(&p, g_tb);    float* tb   = (float*)p;
    cudaGetSymbolAddress(&p, g_agg2);  float* agg2 = (float*)p;
    cudaGetSymbolAddress(&p, g_agg3);  float* agg3 = (float*)p;
    cudaGetSymbolAddress(&p, g_deg0);  int* deg0 = (int*)p;
    cudaGetSymbolAddress(&p, g_deg1);  int* deg1 = (int*)p;
    cudaGetSymbolAddress(&p, g_dega);  int* dega = (int*)p;
    cudaGetSymbolAddress(&p, g_degb);  int* degb = (int*)p;
    cudaGetSymbolAddress(&p, g_cnt0);  int* cnt0 = (int*)p;
    cudaGetSymbolAddress(&p, g_cnt1);  int* cnt1 = (int*)p;
    cudaGetSymbolAddress(&p, g_cnt2);  int* cnt2 = (int*)p;
    cudaGetSymbolAddress(&p, g_cnt3);  int* cnt3 = (int*)p;
    cudaGetSymbolAddress(&p, g_off0);  int* off0 = (int*)p;
    cudaGetSymbolAddress(&p, g_off1);  int* off1 = (int*)p;
    cudaGetSymbolAddress(&p, g_off2);  int* off2 = (int*)p;
    cudaGetSymbolAddress(&p, g_off3);  int* off3 = (int*)p;
    cudaGetSymbolAddress(&p, g_csr0);  int* csr0 = (int*)p;
    cudaGetSymbolAddress(&p, g_csr1);  int* csr1 = (int*)p;
    cudaGetSymbolAddress(&p, g_csr2);  int* csr2 = (int*)p;
    cudaGetSymbolAddress(&p, g_csr3);  int* csr3 = (int*)p;
    cudaGetSymbolAddress(&p, g_part);  int* part = (int*)p;
    cudaGetSymbolAddress(&p, g_W0);    float* W0  = (float*)p;
    cudaGetSymbolAddress(&p, g_W1a);   float* W1a = (float*)p;
    cudaGetSymbolAddress(&p, g_W1b);   float* W1b = (float*)p;
    cudaGetSymbolAddress(&p, g_W2a);   float* W2a = (float*)p;
    cudaGetSymbolAddress(&p, g_W2b);   float* W2b = (float*)p;

    // 1) zero counters
    zero_ints_kernel<<<256, 256>>>();

    // 2) degree histograms
    hist_kernel<<<cdiv(nE[0], 256), 256>>>(e_dst[0], nE[0], deg0);
    hist_kernel<<<cdiv(nE[1], 256), 256>>>(e_dst[1], nE[1], deg1);
    hist_kernel<<<cdiv(nE[2], 256), 256>>>(e_dst[2], nE[2], dega);
    hist_kernel<<<cdiv(nE[3], 256), 256>>>(e_dst[3], nE[3], degb);

    // 3) CSR build per relation
    struct Rel { const int* src; const int* dst; int n; int nd; int* deg; int* off; int* cnt; int* csr; };
    Rel rels[4] = {
        {e_src[0], e_dst[0], nE[0], ND_N, deg0, off0, cnt0, csr0},
        {e_src[1], e_dst[1], nE[1], ND_N, deg1, off1, cnt1, csr1},
        {e_src[2], e_dst[2], nE[2], NA_N, dega, off2, cnt2, csr2},
        {e_src[3], e_dst[3], nE[3], NB_N, degb, off3, cnt3, csr3},
    };
    for (int r = 0; r < 4; r++) {
        int nb = cdiv(rels[r].nd, 1024);
        scan_phase1<<<nb, 1024>>>(rels[r].deg, rels[r].nd, part);
        scan_phase2<<<1, 1>>>(part, nb, rels[r].off, rels[r].nd);
        scan_phase3<<<nb, 1024>>>(rels[r].deg, rels[r].nd, part, rels[r].off);
        scatter_kernel<<<cdiv(rels[r].n, 256), 256>>>(rels[r].src, rels[r].dst, rels[r].n,
                                                      rels[r].off, rels[r].cnt, rels[r].csr);
        sortrows_kernel<<<cdiv(rels[r].nd, 256), 256>>>(rels[r].off, rels[r].csr, rels[r].nd);
    }

    // 4) relation weight matrices from basis decomposition
    build_w_kernel<<<cdiv(128 * 128, 256), 256>>>(basis0, coef0, 0, 128 * 128, W0, 0);
    build_w_kernel<<<cdiv(128 * 128, 256), 256>>>(basis0, coef0, 1, 128 * 128, W0, 128 * 128);
    build_w_kernel<<<cdiv(128 * 128, 256), 256>>>(basis1, coef1, 2, 128 * 128, W1a, 0);
    build_w_kernel<<<cdiv(128 * 128, 256), 256>>>(basis1, coef1, 3, 128 * 128, W1b, 0);
    build_w_kernel<<<cdiv(128 * 16, 256), 256>>>(basis2, coef2, 0, 128 * 16, W2a, 0);
    build_w_kernel<<<cdiv(128 * 16, 256), 256>>>(basis2, coef2, 1, 128 * 16, W2b, 0);

    // 5) layer 0: aggregate feat_a (rel0) / feat_b (rel1) into concat buffer, then GEMM
    agg_csr128_kernel<<<cdiv(ND_N * 32, 256), 256>>>(feat_a, off0, csr0, ND_N, aggd, 256, 0);
    agg_csr128_kernel<<<cdiv(ND_N * 32, 256), 256>>>(feat_b, off1, csr1, ND_N, aggd, 256, 128);
    gemm128_kernel<<<cdiv(ND_N, GTM), 256>>>(aggd, ND_N, 256, deg0, deg1, 128, W0, bias0, 1, h1d);

    // 6) layer 1: aggregate h1_d into 'a' and 'b', transform in place
    agg_csr128_kernel<<<cdiv(NA_N * 32, 256), 256>>>(h1d, off2, csr2, NA_N, ha, 128, 0);
    agg_csr128_kernel<<<cdiv(NB_N * 32, 256), 256>>>(h1d, off3, csr3, NB_N, hb, 128, 0);
    gemm128_kernel<<<cdiv(NA_N, GTM), 256>>>(ha, NA_N, 128, dega, (const int*)0, 128, W1a, bias1, 1, ha);
    gemm128_kernel<<<cdiv(NB_N, GTM), 256>>>(hb, NB_N, 128, degb, (const int*)0, 128, W1b, bias1, 1, hb);

    // 7) layer 2: transform first (dout=16 << 128), then aggregate, then combine
    gemm16_kernel<<<cdiv(NA_N, 32), 256>>>(ha, NA_N, W2a, ta);
    gemm16_kernel<<<cdiv(NB_N, 32), 256>>>(hb, NB_N, W2b, tb);
    agg_csr16_kernel<<<cdiv(ND_N * 4, 256), 256>>>(ta, off0, csr0, ND_N, agg2);
    agg_csr16_kernel<<<cdiv(ND_N * 4, 256), 256>>>(tb, off1, csr1, ND_N, agg3);
    combine_kernel<<<cdiv(ND_N * ODIM, 256), 256>>>(agg2, agg3, deg0, deg1, bias2, out, ND_N * ODIM);
}

// round 2
// speedup vs baseline: 1.4189x; 1.4189x over previous
#include <cuda_runtime.h>
#include <cuda_bf16.h>
#include <cstdint>
#include <cstddef>

#define NA_N 100000
#define NB_N 100000
#define ND_N 50000
#define HDIM 128
#define ODIM 16
#define EMAX 600000

// ------------------------- scratch (static device globals; no allocation) ----
__device__ float g_aggd[(size_t)ND_N * 256];      // layer0 concat aggregates [50000,256]
__device__ float g_h1d[(size_t)ND_N * HDIM];      // h1['d']
__device__ float g_ha[(size_t)NA_N * HDIM];       // agg for 'a' then h2['a'] in-place
__device__ float g_hb[(size_t)NB_N * HDIM];
__device__ float g_ta[(size_t)NA_N * ODIM];       // h2_a @ W2[0]
__device__ float g_tb[(size_t)NB_N * ODIM];
__device__ float g_agg2[(size_t)ND_N * ODIM];
__device__ float g_agg3[(size_t)ND_N * ODIM];

__device__ int g_deg0[ND_N], g_deg1[ND_N], g_dega[NA_N], g_degb[NB_N];
__device__ int g_cnt0[ND_N], g_cnt1[ND_N], g_cnt2[NA_N], g_cnt3[NB_N];
__device__ int g_off0[ND_N + 1], g_off1[ND_N + 1], g_off2[NA_N + 1], g_off3[NB_N + 1];
__device__ int g_csr0[EMAX], g_csr1[EMAX], g_csr2[EMAX], g_csr3[EMAX];
__device__ int g_part[256];

// bf16 hi/lo split weights, TRANSPOSED [out_col][k] for direct B-fragment loads
__device__ __nv_bfloat16 g_W0h[128 * 256], g_W0l[128 * 256];    // layer0, ldk=256
__device__ __nv_bfloat16 g_W1ah[128 * 128], g_W1al[128 * 128];  // W1[2]
__device__ __nv_bfloat16 g_W1bh[128 * 128], g_W1bl[128 * 128];  // W1[3]
__device__ float g_W2a[128 * 16];    // W2[0] fp32 [k][o]
__device__ float g_W2b[128 * 16];    // W2[1]

// ------------------------- small utility kernels -----------------------------
__global__ void zero_ints_kernel() {
    int i = blockIdx.x * blockDim.x + threadIdx.x;
    int st = gridDim.x * blockDim.x;
    for (int j = i; j < ND_N; j += st) { g_deg0[j] = 0; g_deg1[j] = 0; g_cnt0[j] = 0; g_cnt1[j] = 0; }
    for (int j = i; j < NA_N; j += st) { g_dega[j] = 0; g_degb[j] = 0; g_cnt2[j] = 0; g_cnt3[j] = 0; }
}

__global__ void hist_kernel(const int* __restrict__ dst, int n, int* __restrict__ deg) {
    int e = blockIdx.x * blockDim.x + threadIdx.x;
    if (e < n) atomicAdd(&deg[dst[e]], 1);
}

// exclusive scan of deg[0..n) into off[0..n]; 3 phases
__global__ __launch_bounds__(1024) void scan_phase1(const int* __restrict__ deg, int n, int* __restrict__ part) {
    __shared__ int s[1024];
    int i = blockIdx.x * 1024 + threadIdx.x;
    s[threadIdx.x] = (i < n) ? deg[i] : 0;
    __syncthreads();
    for (int o = 512; o > 0; o >>= 1) {
        if (threadIdx.x < o) s[threadIdx.x] += s[threadIdx.x + o];
        __syncthreads();
    }
    if (threadIdx.x == 0) part[blockIdx.x] = s[0];
}

__global__ void scan_phase2(int* part, int nb, int* off, int n) {
    if (threadIdx.x == 0 && blockIdx.x == 0) {
        int run = 0;
        for (int b = 0; b < nb; b++) { int t = part[b]; part[b] = run; run += t; }
        off[n] = run;
    }
}

__global__ __launch_bounds__(1024) void scan_phase3(const int* __restrict__ deg, int n,
                                                    const int* __restrict__ part, int* __restrict__ off) {
    __shared__ int s[1024];
    int tid = threadIdx.x;
    int i = blockIdx.x * 1024 + tid;
    int v = (i < n) ? deg[i] : 0;
    s[tid] = v;
    __syncthreads();
    for (int o = 1; o < 1024; o <<= 1) {
        int t = (tid >= o) ? s[tid - o] : 0;
        __syncthreads();
        s[tid] += t;
        __syncthreads();
    }
    if (i < n) off[i] = part[blockIdx.x] + s[tid] - v;   // exclusive
}

__global__ void scatter_kernel(const int* __restrict__ src, const int* __restrict__ dst, int n,
                               const int* __restrict__ off, int* __restrict__ cnt, int* __restrict__ csr) {
    int e = blockIdx.x * blockDim.x + threadIdx.x;
    if (e < n) {
        int d = dst[e];
        int slot = atomicAdd(&cnt[d], 1);
        csr[off[d] + slot] = src[e];
    }
}

// deterministic order within each dst row (fp-sum order fixed across launches)
__global__ void sortrows_kernel(const int* __restrict__ off, int* __restrict__ csr, int nd) {
    int d = blockIdx.x * blockDim.x + threadIdx.x;
    if (d >= nd) return;
    int b = off[d], e = off[d + 1];
    for (int i = b + 1; i < e; i++) {
        int v = csr[i];
        int j = i - 1;
        while (j >= b && csr[j] > v) { csr[j + 1] = csr[j]; j--; }
        csr[j + 1] = v;
    }
}

// W_r = coef[r,0]*basis[0] + coef[r,1]*basis[1]  -> fp32 [k][o]  (small layer-2 weights)
__global__ void build_w_kernel(const float* __restrict__ basis, const float* __restrict__ coef,
                               int r, int tot, float* __restrict__ out) {
    int idx = blockIdx.x * blockDim.x + threadIdx.x;
    if (idx < tot) {
        float c0 = coef[r * 2 + 0], c1 = coef[r * 2 + 1];
        out[idx] = c0 * basis[idx] + c1 * basis[tot + idx];
    }
}

// bf16 hi/lo split, transposed to [o][k] with leading dim ldk, written at k-offset koff
__global__ void build_wt_kernel(const float* __restrict__ basis, const float* __restrict__ coef,
                                int r, int din, int dout,
                                __nv_bfloat16* __restrict__ Wh, __nv_bfloat16* __restrict__ Wl,
                                int ldk, int koff) {
    int idx = blockIdx.x * blockDim.x + threadIdx.x;
    int tot = din * dout;
    if (idx < tot) {
        int i = idx / dout;   // k (input dim)
        int o = idx % dout;   // output col
        float c0 = coef[r * 2 + 0], c1 = coef[r * 2 + 1];
        float w = c0 * basis[idx] + c1 * basis[tot + idx];
        __nv_bfloat16 h = __float2bfloat16(w);
        float lo = w - __bfloat162float(h);
        Wh[(size_t)o * ldk + koff + i] = h;
        Wl[(size_t)o * ldk + koff + i] = __float2bfloat16(lo);
    }
}

// ------------------------- aggregation (gather-only, no atomics) -------------
__global__ void agg_csr128_kernel(const float* __restrict__ feat, const int* __restrict__ off,
                                  const int* __restrict__ csr, int nd,
                                  float* __restrict__ out, int ldo, int coloff) {
    int warp = (blockIdx.x * blockDim.x + threadIdx.x) >> 5;
    int lane = threadIdx.x & 31;
    if (warp >= nd) return;
    int b = off[warp], e = off[warp + 1];
    float4 acc = make_float4(0.f, 0.f, 0.f, 0.f);
    for (int j = b; j < e; j++) {
        int s = csr[j];
        float4 v = *(const float4*)(feat + (size_t)s * HDIM + lane * 4);
        acc.x += v.x; acc.y += v.y; acc.z += v.z; acc.w += v.w;
    }
    *(float4*)(out + (size_t)warp * ldo + coloff + lane * 4) = acc;
}

__global__ void agg_csr16_kernel(const float* __restrict__ feat, const int* __restrict__ off,
                                 const int* __restrict__ csr, int nd, float* __restrict__ out) {
    int g = (blockIdx.x * blockDim.x + threadIdx.x) >> 2;
    int sl = threadIdx.x & 3;
    if (g >= nd) return;
    int b = off[g], e = off[g + 1];
    float4 acc = make_float4(0.f, 0.f, 0.f, 0.f);
    for (int j = b; j < e; j++) {
        int s = csr[j];
        float4 v = *(const float4*)(feat + (size_t)s * ODIM + sl * 4);
        acc.x += v.x; acc.y += v.y; acc.z += v.z; acc.w += v.w;
    }
    *(float4*)(out + (size_t)g * ODIM + sl * 4) = acc;
}

// ------------------------- GEMM via mma.sync bf16 (hi/lo split) --------------
// Out[M,128] = scale(A[M,K]) @ W[K,128] (+bias, +relu)
// W pre-split to bf16 hi/lo, transposed [n][k]. A split on the fly.
// Accumulate Ah*Wh + Ah*Wl + Al*Wh in fp32 (bf16x3 scheme, ~2^-16 residual).
#define SA 40   // padded smem stride in halves (BK=32 + 8)

#define MMA_BF16(d, a, b)                                                      \
    asm volatile(                                                              \
        "mma.sync.aligned.m16n8k16.row.col.f32.bf16.bf16.f32 "                 \
        "{%0,%1,%2,%3}, {%4,%5,%6,%7}, {%8,%9}, {%0,%1,%2,%3};"                \
        : "+f"(d[0]), "+f"(d[1]), "+f"(d[2]), "+f"(d[3])                       \
        : "r"(a[0]), "r"(a[1]), "r"(a[2]), "r"(a[3]), "r"(b[0]), "r"(b[1]))

__global__ __launch_bounds__(256) void gemm128_mma_kernel(
    const float* __restrict__ A, int M, int K,
    const int* __restrict__ degA, const int* __restrict__ degB, int kHalf,
    const __nv_bfloat16* __restrict__ Wh, const __nv_bfloat16* __restrict__ Wl,
    const float* __restrict__ bias, int doRelu, float* __restrict__ Out)
{
    __shared__ __nv_bfloat16 sAh[128 * SA];
    __shared__ __nv_bfloat16 sAl[128 * SA];
    __shared__ __nv_bfloat16 sBh[128 * SA];
    __shared__ __nv_bfloat16 sBl[128 * SA];
    __shared__ float s0s[128], s1s[128];

    int tid = threadIdx.x;
    int row0 = blockIdx.x * 128;

    if (tid < 128) {
        int r = row0 + tid;
        float a = 1.f, b = 1.f;
        if (r < M) {
            if (degA) a = 1.f / fmaxf((float)degA[r], 1.f);
            if (degB) b = 1.f / fmaxf((float)degB[r], 1.f); else b = a;
        }
        s0s[tid] = a; s1s[tid] = b;
    }
    __syncthreads();

    int warp = tid >> 5, lane = tid & 31;
    int wm = warp >> 2, wn = warp & 3;      // 2 x 4 warp grid; warp tile 64x32
    int g = lane >> 2, t = lane & 3;

    float acc[4][4][4];
#pragma unroll
    for (int mt = 0; mt < 4; mt++)
#pragma unroll
        for (int nt = 0; nt < 4; nt++)
#pragma unroll
            for (int q = 0; q < 4; q++) acc[mt][nt][q] = 0.f;

    for (int k0 = 0; k0 < K; k0 += 32) {
        // --- load & split A tile [128 x 32] (scale folded) ---
#pragma unroll
        for (int l = 0; l < 4; l++) {
            int idx = tid + l * 256;        // 0..1023
            int r = idx >> 3;               // 0..127
            int seg = idx & 7;              // float4 segment
            int gk = k0 + seg * 4;
            float4 v = make_float4(0.f, 0.f, 0.f, 0.f);
            if (row0 + r < M) v = *(const float4*)(A + (size_t)(row0 + r) * K + gk);
            float s = (gk < kHalf) ? s0s[r] : s1s[r];
            v.x *= s; v.y *= s; v.z *= s; v.w *= s;
            __nv_bfloat162 h01 = __floats2bfloat162_rn(v.x, v.y);
            __nv_bfloat162 h23 = __floats2bfloat162_rn(v.z, v.w);
            float l0 = v.x - __bfloat162float(h01.x);
            float l1 = v.y - __bfloat162float(h01.y);
            float l2 = v.z - __bfloat162float(h23.x);
            float l3 = v.w - __bfloat162float(h23.y);
            __nv_bfloat162 lo01 = __floats2bfloat162_rn(l0, l1);
            __nv_bfloat162 lo23 = __floats2bfloat162_rn(l2, l3);
            int base = r * SA + seg * 4;
            *(__nv_bfloat162*)&sAh[base]     = h01;
            *(__nv_bfloat162*)&sAh[base + 2] = h23;
            *(__nv_bfloat162*)&sAl[base]     = lo01;
            *(__nv_bfloat162*)&sAl[base + 2] = lo23;
        }
        // --- load W tiles [128n x 32k] hi/lo (already bf16, transposed) ---
#pragma unroll
        for (int l = 0; l < 8; l++) {
            int idx = tid + l * 256;        // 0..2047
            int n = idx >> 4;               // 0..127
            int j = idx & 15;               // u32 (2 halves) within chunk
            *(uint32_t*)&sBh[n * SA + j * 2] = *(const uint32_t*)&Wh[(size_t)n * K + k0 + j * 2];
            *(uint32_t*)&sBl[n * SA + j * 2] = *(const uint32_t*)&Wl[(size_t)n * K + k0 + j * 2];
        }
        __syncthreads();

#pragma unroll
        for (int ks = 0; ks < 2; ks++) {
            int kb = ks * 16;
            uint32_t ah[4][4], al[4][4];
#pragma unroll
            for (int mt = 0; mt < 4; mt++) {
                int r = (wm * 64 + mt * 16 + g) * SA + kb + 2 * t;
                ah[mt][0] = *(uint32_t*)&sAh[r];
                ah[mt][1] = *(uint32_t*)&sAh[r + 8 * SA];
                ah[mt][2] = *(uint32_t*)&sAh[r + 8];
                ah[mt][3] = *(uint32_t*)&sAh[r + 8 * SA + 8];
                al[mt][0] = *(uint32_t*)&sAl[r];
                al[mt][1] = *(uint32_t*)&sAl[r + 8 * SA];
                al[mt][2] = *(uint32_t*)&sAl[r + 8];
                al[mt][3] = *(uint32_t*)&sAl[r + 8 * SA + 8];
            }
            uint32_t bh[4][2], bl[4][2];
#pragma unroll
            for (int nt = 0; nt < 4; nt++) {
                int n = (wn * 32 + nt * 8 + g) * SA + kb + 2 * t;
                bh[nt][0] = *(uint32_t*)&sBh[n];
                bh[nt][1] = *(uint32_t*)&sBh[n + 8];
                bl[nt][0] = *(uint32_t*)&sBl[n];
                bl[nt][1] = *(uint32_t*)&sBl[n + 8];
            }
#pragma unroll
            for (int mt = 0; mt < 4; mt++)
#pragma unroll
                for (int nt = 0; nt < 4; nt++) {
                    MMA_BF16(acc[mt][nt], ah[mt], bh[nt]);
                    MMA_BF16(acc[mt][nt], ah[mt], bl[nt]);
                    MMA_BF16(acc[mt][nt], al[mt], bh[nt]);
                }
        }
        __syncthreads();
    }

    // --- epilogue: bias + relu, write fp32 ---
#pragma unroll
    for (int mt = 0; mt < 4; mt++) {
#pragma unroll
        for (int nt = 0; nt < 4; nt++) {
            int r = row0 + wm * 64 + mt * 16 + g;
            int c = wn * 32 + nt * 8 + 2 * t;
            float b0 = bias[c], b1 = bias[c + 1];
            float v0 = acc[mt][nt][0] + b0;
            float v1 = acc[mt][nt][1] + b1;
            float v2 = acc[mt][nt][2] + b0;
            float v3 = acc[mt][nt][3] + b1;
            if (doRelu) {
                v0 = fmaxf(v0, 0.f); v1 = fmaxf(v1, 0.f);
                v2 = fmaxf(v2, 0.f); v3 = fmaxf(v3, 0.f);
            }
            if (r < M)     *(float2*)(Out + (size_t)r * 128 + c)       = make_float2(v0, v1);
            if (r + 8 < M) *(float2*)(Out + (size_t)(r + 8) * 128 + c) = make_float2(v2, v3);
        }
    }
}

// Out[M,16] = A[M,128] @ W[128,16]  (no bias/relu/scale)
__global__ __launch_bounds__(256) void gemm16_kernel(const float* __restrict__ A, int M,
                                                     const float* __restrict__ W, float* __restrict__ Out) {
    __shared__ float As[32][132];
    __shared__ float Wt[16][132];
    int tid = threadIdx.x;
    for (int idx = tid; idx < 2048; idx += 256) {
        int k = idx >> 4, c = idx & 15;
        Wt[c][k] = W[idx];
    }
    int row0 = blockIdx.x * 32;
#pragma unroll
    for (int l = 0; l < 4; l++) {
        int idx = tid + l * 256;
        int r = idx >> 5;
        int kv = idx & 31;
        float4 v = make_float4(0.f, 0.f, 0.f, 0.f);
        if (row0 + r < M) v = *(const float4*)(A + (size_t)(row0 + r) * 128 + kv * 4);
        *(float4*)&As[r][kv * 4] = v;
    }
    __syncthreads();
    int r = tid >> 4;   // 0..15 (rows r and r+16)
    int c = tid & 15;
    float acc0 = 0.f, acc1 = 0.f;
#pragma unroll
    for (int k = 0; k < 128; k += 4) {
        float4 w = *(float4*)&Wt[c][k];
        float4 a0 = *(float4*)&As[r][k];
        float4 a1 = *(float4*)&As[r + 16][k];
        acc0 += a0.x * w.x + a0.y * w.y + a0.z * w.z + a0.w * w.w;
        acc1 += a1.x * w.x + a1.y * w.y + a1.z * w.z + a1.w * w.w;
    }
    if (row0 + r < M)      Out[(size_t)(row0 + r) * 16 + c] = acc0;
    if (row0 + r + 16 < M) Out[(size_t)(row0 + r + 16) * 16 + c] = acc1;
}

// out[i,c] = agg2[i,c]/max(deg0,1) + agg3[i,c]/max(deg1,1) + bias2[c]
__global__ void combine_kernel(const float* __restrict__ agg2, const float* __restrict__ agg3,
                               const int* __restrict__ deg0, const int* __restrict__ deg1,
                               const float* __restrict__ bias2, float* __restrict__ out, int n) {
    int idx = blockIdx.x * blockDim.x + threadIdx.x;
    if (idx >= n) return;
    int i = idx >> 4;
    int c = idx & 15;
    float inv0 = 1.f / fmaxf((float)deg0[i], 1.f);
    float inv1 = 1.f / fmaxf((float)deg1[i], 1.f);
    out[idx] = agg2[idx] * inv0 + agg3[idx] * inv1 + bias2[c];
}

// ------------------------- host driver ---------------------------------------
static inline int cdiv(int a, int b) { return (a + b - 1) / b; }

extern "C" void kernel_launch(void* const* d_in, const int* in_sizes, int n_in,
                              void* d_out, int out_size) {
    (void)n_in; (void)out_size;
    const float* feat_a = (const float*)d_in[0];
    const float* feat_b = (const float*)d_in[1];
    const float* basis0 = (const float*)d_in[3];
    const float* coef0  = (const float*)d_in[4];
    const float* bias0  = (const float*)d_in[5];
    const float* basis1 = (const float*)d_in[6];
    const float* coef1  = (const float*)d_in[7];
    const float* bias1  = (const float*)d_in[8];
    const float* basis2 = (const float*)d_in[9];
    const float* coef2  = (const float*)d_in[10];
    const float* bias2  = (const float*)d_in[11];
    const int* e_src[4] = {(const int*)d_in[12], (const int*)d_in[14], (const int*)d_in[16], (const int*)d_in[18]};
    const int* e_dst[4] = {(const int*)d_in[13], (const int*)d_in[15], (const int*)d_in[17], (const int*)d_in[19]};
    int nE[4] = {in_sizes[12], in_sizes[14], in_sizes[16], in_sizes[18]};
    float* out = (float*)d_out;

    void* p;
    cudaGetSymbolAddress(&p, g_aggd);  float* aggd = (float*)p;
    cudaGetSymbolAddress(&p, g_h1d);   float* h1d  = (float*)p;
    cudaGetSymbolAddress(&p, g_ha);    float* ha   = (float*)p;
    cudaGetSymbolAddress(&p, g_hb);    float* hb   = (float*)p;
    cudaGetSymbolAddress(&p, g_ta);    float* ta   = (float*)p;
    cudaGetSymbolAddress(&p, g_tb);    float* tb   = (float*)p;
    cudaGetSymbolAddress(&p, g_agg2);  float* agg2 = (float*)p;
    cudaGetSymbolAddress(&p, g_agg3);  float* agg3 = (float*)p;
    cudaGetSymbolAddress(&p, g_deg0);  int* deg0 = (int*)p;
    cudaGetSymbolAddress(&p, g_deg1);  int* deg1 = (int*)p;
    cudaGetSymbolAddress(&p, g_dega);  int* dega = (int*)p;
    cudaGetSymbolAddress(&p, g_degb);  int* degb = (int*)p;
    cudaGetSymbolAddress(&p, g_cnt0);  int* cnt0 = (int*)p;
    cudaGetSymbolAddress(&p, g_cnt1);  int* cnt1 = (int*)p;
    cudaGetSymbolAddress(&p, g_cnt2);  int* cnt2 = (int*)p;
    cudaGetSymbolAddress(&p, g_cnt3);  int* cnt3 = (int*)p;
    cudaGetSymbolAddress(&p, g_off0);  int* off0 = (int*)p;
    cudaGetSymbolAddress(&p, g_off1);  int* off1 = (int*)p;
    cudaGetSymbolAddress(&p, g_off2);  int* off2 = (int*)p;
    cudaGetSymbolAddress(&p, g_off3);  int* off3 = (int*)p;
    cudaGetSymbolAddress(&p, g_csr0);  int* csr0 = (int*)p;
    cudaGetSymbolAddress(&p, g_csr1);  int* csr1 = (int*)p;
    cudaGetSymbolAddress(&p, g_csr2);  int* csr2 = (int*)p;
    cudaGetSymbolAddress(&p, g_csr3);  int* csr3 = (int*)p;
    cudaGetSymbolAddress(&p, g_part);  int* part = (int*)p;
    cudaGetSymbolAddress(&p, g_W0h);   __nv_bfloat16* W0h  = (__nv_bfloat16*)p;
    cudaGetSymbolAddress(&p, g_W0l);   __nv_bfloat16* W0l  = (__nv_bfloat16*)p;
    cudaGetSymbolAddress(&p, g_W1ah);  __nv_bfloat16* W1ah = (__nv_bfloat16*)p;
    cudaGetSymbolAddress(&p, g_W1al);  __nv_bfloat16* W1al = (__nv_bfloat16*)p;
    cudaGetSymbolAddress(&p, g_W1bh);  __nv_bfloat16* W1bh = (__nv_bfloat16*)p;
    cudaGetSymbolAddress(&p, g_W1bl);  __nv_bfloat16* W1bl = (__nv_bfloat16*)p;
    cudaGetSymbolAddress(&p, g_W2a);   float* W2a = (float*)p;
    cudaGetSymbolAddress(&p, g_W2b);   float* W2b = (float*)p;

    // 1) zero counters
    zero_ints_kernel<<<256, 256>>>();

    // 2) degree histograms
    hist_kernel<<<cdiv(nE[0], 256), 256>>>(e_dst[0], nE[0], deg0);
    hist_kernel<<<cdiv(nE[1], 256), 256>>>(e_dst[1], nE[1], deg1);
    hist_kernel<<<cdiv(nE[2], 256), 256>>>(e_dst[2], nE[2], dega);
    hist_kernel<<<cdiv(nE[3], 256), 256>>>(e_dst[3], nE[3], degb);

    // 3) CSR build per relation
    struct Rel { const int* src; const int* dst; int n; int nd; int* deg; int* off; int* cnt; int* csr; };
    Rel rels[4] = {
        {e_src[0], e_dst[0], nE[0], ND_N, deg0, off0, cnt0, csr0},
        {e_src[1], e_dst[1], nE[1], ND_N, deg1, off1, cnt1, csr1},
        {e_src[2], e_dst[2], nE[2], NA_N, dega, off2, cnt2, csr2},
        {e_src[3], e_dst[3], nE[3], NB_N, degb, off3, cnt3, csr3},
    };
    for (int r = 0; r < 4; r++) {
        int nb = cdiv(rels[r].nd, 1024);
        scan_phase1<<<nb, 1024>>>(rels[r].deg, rels[r].nd, part);
        scan_phase2<<<1, 1>>>(part, nb, rels[r].off, rels[r].nd);
        scan_phase3<<<nb, 1024>>>(rels[r].deg, rels[r].nd, part, rels[r].off);
        scatter_kernel<<<cdiv(rels[r].n, 256), 256>>>(rels[r].src, rels[r].dst, rels[r].n,
                                                      rels[r].off, rels[r].cnt, rels[r].csr);
        sortrows_kernel<<<cdiv(rels[r].nd, 256), 256>>>(rels[r].off, rels[r].csr, rels[r].nd);
    }

    // 4) relation weights: bf16 hi/lo transposed for mma GEMMs, fp32 for layer-2
    build_wt_kernel<<<cdiv(128 * 128, 256), 256>>>(basis0, coef0, 0, 128, 128, W0h, W0l, 256, 0);
    build_wt_kernel<<<cdiv(128 * 128, 256), 256>>>(basis0, coef0, 1, 128, 128, W0h, W0l, 256, 128);
    build_wt_kernel<<<cdiv(128 * 128, 256), 256>>>(basis1, coef1, 2, 128, 128, W1ah, W1al, 128, 0);
    build_wt_kernel<<<cdiv(128 * 128, 256), 256>>>(basis1, coef1, 3, 128, 128, W1bh, W1bl, 128, 0);
    build_w_kernel<<<cdiv(128 * 16, 256), 256>>>(basis2, coef2, 0, 128 * 16, W2a);
    build_w_kernel<<<cdiv(128 * 16, 256), 256>>>(basis2, coef2, 1, 128 * 16, W2b);

    // 5) layer 0: aggregate feat_a (rel0) / feat_b (rel1) into concat buffer, then GEMM
    agg_csr128_kernel<<<cdiv(ND_N * 32, 256), 256>>>(feat_a, off0, csr0, ND_N, aggd, 256, 0);
    agg_csr128_kernel<<<cdiv(ND_N * 32, 256), 256>>>(feat_b, off1, csr1, ND_N, aggd, 256, 128);
    gemm128_mma_kernel<<<cdiv(ND_N, 128), 256>>>(aggd, ND_N, 256, deg0, deg1, 128, W0h, W0l, bias0, 1, h1d);

    // 6) layer 1: aggregate h1_d into 'a' and 'b', transform in place
    agg_csr128_kernel<<<cdiv(NA_N * 32, 256), 256>>>(h1d, off2, csr2, NA_N, ha, 128, 0);
    agg_csr128_kernel<<<cdiv(NB_N * 32, 256), 256>>>(h1d, off3, csr3, NB_N, hb, 128, 0);
    gemm128_mma_kernel<<<cdiv(NA_N, 128), 256>>>(ha, NA_N, 128, dega, (const int*)0, 128, W1ah, W1al, bias1, 1, ha);
    gemm128_mma_kernel<<<cdiv(NB_N, 128), 256>>>(hb, NB_N, 128, degb, (const int*)0, 128, W1bh, W1bl, bias1, 1, hb);

    // 7) layer 2: transform first (dout=16 << 128), then aggregate, then combine
    gemm16_kernel<<<cdiv(NA_N, 32), 256>>>(ha, NA_N, W2a, ta);
    gemm16_kernel<<<cdiv(NB_N, 32), 256>>>(hb, NB_N, W2b, tb);
    agg_csr16_kernel<<<cdiv(ND_N * 4, 256), 256>>>(ta, off0, csr0, ND_N, agg2);
    agg_csr16_kernel<<<cdiv(ND_N * 4, 256), 256>>>(tb, off1, csr1, ND_N, agg3);
    combine_kernel<<<cdiv(ND_N * ODIM, 256), 256>>>(agg2, agg3, deg0, deg1, bias2, out, ND_N * ODIM);
}